// round 15
// baseline (speedup 1.0000x reference)
#include <cuda_runtime.h>
#include <math.h>
#include <stdint.h>

#define KMIX 32
#define DDIM 32
#define TILE 512
#define NTH  256
#define XSTR 36   // padded row stride (floats)

// ---- smem float offsets ----
#define OFF_B   0                       // 32768 f : B fragments (128KB)
#define OFF_X   32768                   // 18432 f : X tile [512 x XSTR]; NLL overlays after A-frag load
#define OFF_NTP (OFF_X + TILE * XSTR)   // 1024 f : -t pairs (512 float2)
#define OFF_C   (OFF_NTP + 1024)        // 32 f
#define SMEM_FLOATS (OFF_C + 32)

#define OFF_NLL OFF_X                   // overlay

// ---- device-global precomputed data (no allocation) ----
__device__ float2 g_bfrag[KMIX * 4 * 4 * 32]; // [k][cb][kc][lane]
__device__ float2 g_ntp[KMIX * 16];           // [k][c2] = {-t[2c2], -t[2c2+1]}
__device__ float  g_c[KMIX];

// ---------------- helpers ----------------
static __device__ __forceinline__ float tf32r(float x) {
    uint32_t r; asm("cvt.rna.tf32.f32 %0, %1;" : "=r"(r) : "f"(x));
    return __uint_as_float(r);
}
static __device__ __forceinline__ unsigned long long fma2(unsigned long long a,
                                                          unsigned long long b,
                                                          unsigned long long c) {
    unsigned long long d;
    asm("fma.rn.f32x2 %0, %1, %2, %3;" : "=l"(d) : "l"(a), "l"(b), "l"(c));
    return d;
}
static __device__ __forceinline__ unsigned long long add2(unsigned long long a,
                                                          unsigned long long b) {
    unsigned long long d;
    asm("add.rn.f32x2 %0, %1, %2;" : "=l"(d) : "l"(a), "l"(b));
    return d;
}
static __device__ __forceinline__ float hadd2(unsigned long long a) {
    float lo, hi;
    asm("mov.b64 {%0, %1}, %2;" : "=f"(lo), "=f"(hi) : "l"(a));
    return lo + hi;
}
static __device__ __forceinline__ unsigned long long pack2f(float lo, float hi) {
    unsigned long long d;
    asm("mov.b64 %0, {%1, %2};" : "=l"(d) : "f"(lo), "f"(hi));
    return d;
}

#define MMA_TF32(c0, c1, c2, c3, a0, a1, a2, a3, b0, b1)                         \
    asm volatile("mma.sync.aligned.m16n8k8.row.col.f32.tf32.tf32.f32 "           \
                 "{%0,%1,%2,%3}, {%4,%5,%6,%7}, {%8,%9}, {%0,%1,%2,%3};"         \
                 : "+f"(c0), "+f"(c1), "+f"(c2), "+f"(c3)                        \
                 : "r"(a0), "r"(a1), "r"(a2), "r"(a3), "r"(b0), "r"(b1))

// ---------------- precompute: one warp per mixture ----------------
__global__ void gmm_pre(const float* __restrict__ sigmas,
                        const float* __restrict__ mus,
                        const float* __restrict__ phis) {
    __shared__ float sL[1024];
    __shared__ float sMi[1024];
    __shared__ float sT[32];
    int k = blockIdx.x;
    int lane = threadIdx.x;
    int gid = lane >> 2, tig = lane & 3;

    for (int idx = lane; idx < 1024; idx += 32) {
        sL[idx] = sigmas[k * 1024 + idx];
        sMi[idx] = 0.0f;
    }
    __syncwarp();

    for (int j = 0; j < DDIM; j++) {
        float s = 0.0f;
        if (lane >= j) {
            s = sL[lane * 32 + j];
            for (int p = 0; p < j; p++) s -= sL[lane * 32 + p] * sL[j * 32 + p];
        }
        __syncwarp();
        if (lane == j) sL[j * 32 + j] = sqrtf(s);
        __syncwarp();
        if (lane > j) sL[lane * 32 + j] = s / sL[j * 32 + j];
        __syncwarp();
    }
    {
        int c = lane;
        for (int i = c; i < DDIM; i++) {
            float s = (i == c) ? 1.0f : 0.0f;
            for (int p = c; p < i; p++) s -= sL[i * 32 + p] * sMi[p * 32 + c];
            sMi[i * 32 + c] = s / sL[i * 32 + i];
        }
    }
    __syncwarp();
    for (int idx = lane; idx < 1024; idx += 32) {
        int i = idx >> 5, j = idx & 31;
        sMi[idx] = (j <= i) ? tf32r(sMi[idx]) : 0.0f;
    }
    __syncwarp();

#pragma unroll
    for (int cb = 0; cb < 4; cb++)
#pragma unroll
        for (int kc = 0; kc < 4; kc++)
            g_bfrag[((k * 4 + cb) * 4 + kc) * 32 + lane] =
                make_float2(sMi[(cb * 8 + gid) * 32 + kc * 8 + tig],
                            sMi[(cb * 8 + gid) * 32 + kc * 8 + tig + 4]);

    {
        float tv = 0.0f;
        for (int j = 0; j <= lane; j++) tv = fmaf(sMi[lane * 32 + j], mus[k * 32 + j], tv);
        sT[lane] = tv;
    }
    __syncwarp();
    if (lane < 16)
        g_ntp[k * 16 + lane] = make_float2(-sT[2 * lane], -sT[2 * lane + 1]);

    if (lane == 0) {
        float logdet = 0.0f;
        for (int j = 0; j < DDIM; j++) logdet += logf(sL[j * 32 + j]);
        logdet *= 2.0f;
        const float log2pi = 1.8378770664093453f;
        g_c[k] = -logf(phis[k]) + 0.5f * ((float)DDIM * log2pi + logdet);
    }
}

// ---------------- main: persistent tensor-core kernel ----------------
__global__ void __launch_bounds__(NTH, 1)
gmm_tc(const float* __restrict__ X, float* __restrict__ out, int N, int tiles) {
    extern __shared__ float sh[];
    const int tid = threadIdx.x;
    const int wid = tid >> 5;
    const int lane = tid & 31;
    const int gid = lane >> 2, tig = lane & 3;

    // stage constants once
    {
        const float4* src = reinterpret_cast<const float4*>(g_bfrag);
        float4* dst = reinterpret_cast<float4*>(sh + OFF_B);
        for (int i = tid; i < (KMIX * 4 * 4 * 32) / 2; i += NTH) dst[i] = src[i];
        const float4* s2 = reinterpret_cast<const float4*>(g_ntp);
        float4* d2 = reinterpret_cast<float4*>(sh + OFF_NTP);
        for (int i = tid; i < (KMIX * 16) / 2; i += NTH) d2[i] = s2[i];
        if (tid < KMIX) sh[OFF_C + tid] = g_c[tid];
    }
    __syncthreads();

    const unsigned long long* sB   = reinterpret_cast<const unsigned long long*>(sh + OFF_B);
    const unsigned long long* sNtp = reinterpret_cast<const unsigned long long*>(sh + OFF_NTP);

    for (int tile = blockIdx.x; tile < tiles; tile += gridDim.x) {
        // stage X tile (tf32-rounded), two rows per thread
#pragma unroll
        for (int h = 0; h < 2; h++) {
            int r = h * NTH + tid;
            int n = tile * TILE + r;
            if (n >= N) n = N - 1;
            const float4* xr = reinterpret_cast<const float4*>(X + (size_t)n * DDIM);
            float* xd = sh + OFF_X + r * XSTR;
#pragma unroll
            for (int j = 0; j < 8; j++) {
                float4 v = xr[j];
                v.x = tf32r(v.x); v.y = tf32r(v.y); v.z = tf32r(v.z); v.w = tf32r(v.w);
                *reinterpret_cast<float4*>(xd + 4 * j) = v;
            }
        }
        __syncthreads();

        // A fragments: warp owns rows [wid*64, wid*64+64), four m16 row-blocks
        uint32_t a[4][4][4];
        {
            const float* xs = sh + OFF_X;
#pragma unroll
            for (int rb = 0; rb < 4; rb++) {
                int rowbase = wid * 64 + rb * 16;
#pragma unroll
                for (int kc = 0; kc < 4; kc++) {
                    a[rb][kc][0] = __float_as_uint(xs[(rowbase + gid) * XSTR + kc * 8 + tig]);
                    a[rb][kc][1] = __float_as_uint(xs[(rowbase + gid + 8) * XSTR + kc * 8 + tig]);
                    a[rb][kc][2] = __float_as_uint(xs[(rowbase + gid) * XSTR + kc * 8 + tig + 4]);
                    a[rb][kc][3] = __float_as_uint(xs[(rowbase + gid + 8) * XSTR + kc * 8 + tig + 4]);
                }
            }
        }
        __syncwarp();   // all X reads of this warp's rows done before NLL overlay writes

#pragma unroll 1
        for (int k = 0; k < KMIX; k++) {
            const unsigned long long* bk = sB + k * 512;
            unsigned long long q[4][2];
#pragma unroll
            for (int rb = 0; rb < 4; rb++) { q[rb][0] = 0ull; q[rb][1] = 0ull; }
#pragma unroll
            for (int cb = 0; cb < 4; cb++) {
                float c[4][4];
#pragma unroll
                for (int rb = 0; rb < 4; rb++)
#pragma unroll
                    for (int j = 0; j < 4; j++) c[rb][j] = 0.0f;
#pragma unroll
                for (int kc = 0; kc < 4; kc++) {
                    unsigned long long b = bk[(cb * 4 + kc) * 32 + lane];
                    uint32_t b0 = (uint32_t)b, b1 = (uint32_t)(b >> 32);
#pragma unroll
                    for (int rb = 0; rb < 4; rb++)
                        MMA_TF32(c[rb][0], c[rb][1], c[rb][2], c[rb][3],
                                 a[rb][kc][0], a[rb][kc][1], a[rb][kc][2], a[rb][kc][3],
                                 b0, b1);
                }
                unsigned long long nt = sNtp[k * 16 + cb * 4 + tig];
#pragma unroll
                for (int rb = 0; rb < 4; rb++) {
                    unsigned long long y;
                    y = add2(pack2f(c[rb][0], c[rb][1]), nt); q[rb][0] = fma2(y, y, q[rb][0]);
                    y = add2(pack2f(c[rb][2], c[rb][3]), nt); q[rb][1] = fma2(y, y, q[rb][1]);
                }
            }
            float ck = sh[OFF_C + k];
#pragma unroll
            for (int rb = 0; rb < 4; rb++) {
                float ql = hadd2(q[rb][0]);
                float qh = hadd2(q[rb][1]);
                ql += __shfl_xor_sync(0xffffffffu, ql, 1);
                ql += __shfl_xor_sync(0xffffffffu, ql, 2);
                qh += __shfl_xor_sync(0xffffffffu, qh, 1);
                qh += __shfl_xor_sync(0xffffffffu, qh, 2);
                if (tig == 0) {
                    int rowbase = wid * 64 + rb * 16;
                    sh[OFF_NLL + (rowbase + gid) * XSTR + k]     = fmaf(0.5f, ql, ck);
                    sh[OFF_NLL + (rowbase + gid + 8) * XSTR + k] = fmaf(0.5f, qh, ck);
                }
            }
        }
        __syncthreads();

        // output: two rows per thread, row-max normalize
#pragma unroll
        for (int h = 0; h < 2; h++) {
            int r = h * NTH + tid;
            int n = tile * TILE + r;
            if (n < N) {
                const float* row = sh + OFF_NLL + r * XSTR;
                float v[32];
                float mx = -3.0e38f;
#pragma unroll
                for (int j = 0; j < 32; j++) { v[j] = row[j]; mx = fmaxf(mx, v[j]); }
                float inv = 1.0f / mx;
                float4* op = reinterpret_cast<float4*>(out + (size_t)n * DDIM);
#pragma unroll
                for (int j = 0; j < 8; j++)
                    op[j] = make_float4(v[4 * j] * inv, v[4 * j + 1] * inv,
                                        v[4 * j + 2] * inv, v[4 * j + 3] * inv);
            }
        }
        __syncthreads();
    }
}

extern "C" void kernel_launch(void* const* d_in, const int* in_sizes, int n_in,
                              void* d_out, int out_size) {
    const float* X      = (const float*)d_in[0];
    const float* mus    = (const float*)d_in[1];
    const float* sigmas = (const float*)d_in[2];
    const float* phis   = (const float*)d_in[3];
    float* out = (float*)d_out;

    int N = in_sizes[0] / DDIM;
    int tiles = (N + TILE - 1) / TILE;

    static int smCount = 0;
    if (smCount == 0) {
        cudaDeviceGetAttribute(&smCount, cudaDevAttrMultiProcessorCount, 0);
        if (smCount <= 0) smCount = 148;
    }
    int grid = tiles < smCount ? tiles : smCount;

    gmm_pre<<<KMIX, 32>>>(sigmas, mus, phis);

    size_t shmem = (size_t)SMEM_FLOATS * sizeof(float);
    cudaFuncSetAttribute((const void*)gmm_tc,
                         cudaFuncAttributeMaxDynamicSharedMemorySize, (int)shmem);
    gmm_tc<<<grid, NTH, shmem>>>(X, out, N, tiles);
}